// round 9
// baseline (speedup 1.0000x reference)
#include <cuda_runtime.h>
#include <cuda_fp16.h>
#include <cstdint>

#define NPIX    65536
#define HW      1024
#define DIM     64
#define KCODES  512
#define NHALF   256          // codes per CTA
#define TILE_M  128          // pixels per tile
#define NTILES  512
#define NSLOTS  148
#define GRID    (2 * NSLOTS)
#define THREADS 256

// smem byte offsets; rows padded to 144B (72 halves) -> conflict-free ldmatrix
#define ROWB    144
#define OFF_AHI 0
#define OFF_ALO (OFF_AHI + TILE_M * ROWB)   // 18432
#define OFF_BHI (OFF_ALO + TILE_M * ROWB)   // 36864
#define OFF_BLO (OFF_BHI + NHALF * ROWB)    // 73728
#define OFF_E2  (OFF_BLO + NHALF * ROWB)    // 110592
#define SMEM_SZ (OFF_E2 + NHALF * 4)        // 111616

__device__ float g_best[2 * NPIX];
__device__ int   g_bidx[2 * NPIX];

static __device__ __forceinline__ uint32_t s2u(const void* p) {
    uint32_t a;
    asm("{ .reg .u64 t; cvta.to.shared.u64 t, %1; cvt.u32.u64 %0, t; }"
        : "=r"(a) : "l"(p));
    return a;
}

#define LDSM_X4(r, addr) \
    asm volatile("ldmatrix.sync.aligned.m8n8.x4.shared.b16 {%0,%1,%2,%3}, [%4];" \
        : "=r"((r)[0]), "=r"((r)[1]), "=r"((r)[2]), "=r"((r)[3]) : "r"(addr))

static __device__ __forceinline__ void mma16816(float* d, const uint32_t* a,
                                                const uint32_t* b) {
    asm volatile(
        "mma.sync.aligned.m16n8k16.row.col.f32.f16.f16.f32 "
        "{%0,%1,%2,%3}, {%4,%5,%6,%7}, {%8,%9}, {%0,%1,%2,%3};"
        : "+f"(d[0]), "+f"(d[1]), "+f"(d[2]), "+f"(d[3])
        : "r"(a[0]), "r"(a[1]), "r"(a[2]), "r"(a[3]), "r"(b[0]), "r"(b[1]));
}

// fp16-accumulator variant for the small correction terms
static __device__ __forceinline__ void mmah16816(uint32_t* d, const uint32_t* a,
                                                 const uint32_t* b) {
    asm volatile(
        "mma.sync.aligned.m16n8k16.row.col.f16.f16.f16.f16 "
        "{%0,%1}, {%2,%3,%4,%5}, {%6,%7}, {%0,%1};"
        : "+r"(d[0]), "+r"(d[1])
        : "r"(a[0]), "r"(a[1]), "r"(a[2]), "r"(a[3]), "r"(b[0]), "r"(b[1]));
}

__global__ void __launch_bounds__(THREADS, 2)
vq_main(const float* __restrict__ x, const float* __restrict__ cb) {
    extern __shared__ char smem[];
    const uint32_t sb = s2u(smem);
    const int tid  = threadIdx.x;
    const int wid  = tid >> 5, lane = tid & 31;

    const int half  = blockIdx.x & 1;
    const int slot  = blockIdx.x >> 1;
    const int kbase = half * NHALF;

    // ---- stage B half (256 codes) as fp16 hi/lo, padded rows ----
    {
        const float4* cb4 = reinterpret_cast<const float4*>(cb + kbase * DIM);
#pragma unroll
        for (int i = 0; i < (NHALF * DIM / 4) / THREADS; i++) {   // 16 iters
            int idx = i * THREADS + tid;          // 0..4095
            int kr = idx >> 4, d4 = idx & 15;
            float4 v = cb4[idx];
            __half hh[4], ll[4];
            hh[0] = __float2half_rn(v.x); ll[0] = __float2half_rn(v.x - __half2float(hh[0]));
            hh[1] = __float2half_rn(v.y); ll[1] = __float2half_rn(v.y - __half2float(hh[1]));
            hh[2] = __float2half_rn(v.z); ll[2] = __float2half_rn(v.z - __half2float(hh[2]));
            hh[3] = __float2half_rn(v.w); ll[3] = __float2half_rn(v.w - __half2float(hh[3]));
            uint32_t off = kr * ROWB + d4 * 8;
            *(uint2*)(smem + OFF_BHI + off) = *(const uint2*)hh;
            *(uint2*)(smem + OFF_BLO + off) = *(const uint2*)ll;
        }
        // inline e2: thread k computes 0.5*||code_{kbase+k}||^2 (L2-hot re-read)
        const float4* row = reinterpret_cast<const float4*>(cb + (kbase + tid) * DIM);
        float s = 0.f;
#pragma unroll
        for (int j = 0; j < DIM / 4; j++) {
            float4 v = row[j];
            s = fmaf(v.x, v.x, s);
            s = fmaf(v.y, v.y, s);
            s = fmaf(v.z, v.z, s);
            s = fmaf(v.w, v.w, s);
        }
        ((float*)(smem + OFF_E2))[tid] = 0.5f * s;
    }
    __syncthreads();

    const float* se2 = (const float*)(smem + OFF_E2);
    const int R0 = wid * 16;   // warp's pixel-row base within tile

    for (int t = slot; t < NTILES; t += NSLOTS) {
        const int P0  = t * TILE_M;
        const int b   = P0 >> 10;
        const int nl0 = P0 & (HW - 1);
        const float* src = x + (size_t)b * DIM * HW + nl0;

        // ---- stage A tile (128 px x 64 d) fp16 hi/lo, [pixel][dim] ----
        {
            const int row = tid & 127;
            const int d0  = (tid >> 7) * 32;
#pragma unroll
            for (int blk = 0; blk < 4; blk++) {
                __half hh[8], ll[8];
#pragma unroll
                for (int j = 0; j < 8; j++) {
                    float v = src[(size_t)(d0 + blk * 8 + j) * HW + row];
                    hh[j] = __float2half_rn(v);
                    ll[j] = __float2half_rn(v - __half2float(hh[j]));
                }
                uint32_t off = row * ROWB + (d0 + blk * 8) * 2;
                *(uint4*)(smem + OFF_AHI + off) = *(const uint4*)hh;
                *(uint4*)(smem + OFF_ALO + off) = *(const uint4*)ll;
            }
        }
        __syncthreads();

        float best0 = 3.4e38f, best1 = 3.4e38f;
        int   bi0 = 0, bi1 = 0;

        // A ldmatrix address: lane -> row R0+(lane&15), col-half (lane>>4)
        const uint32_t aoff = (R0 + (lane & 15)) * ROWB + (lane >> 4) * 16;
        // B ldmatrix address: lane -> code row (lane&7), 16B chunk (lane>>3)
        const uint32_t boff_lane = (lane & 7) * ROWB + (lane >> 3) * 16;

#pragma unroll
        for (int c0 = 0; c0 < NHALF; c0 += 64) {      // 4 chunks of 64 codes
            // A fragments for all 4 k-steps (full 64 dims), hi + lo
            uint32_t ah[4][4], al[4][4];
#pragma unroll
            for (int ks = 0; ks < 4; ks++) {
                LDSM_X4(ah[ks], sb + OFF_AHI + aoff + ks * 32);
                LDSM_X4(al[ks], sb + OFF_ALO + aoff + ks * 32);
            }

#pragma unroll
            for (int nt = 0; nt < 8; nt++) {
                uint32_t bb = (c0 + nt * 8) * ROWB + boff_lane;
                uint32_t bh[8], bl[8];
                LDSM_X4(bh,     sb + OFF_BHI + bb);        // ksteps 0,1
                LDSM_X4(bh + 4, sb + OFF_BHI + bb + 64);   // ksteps 2,3
                LDSM_X4(bl,     sb + OFF_BLO + bb);
                LDSM_X4(bl + 4, sb + OFF_BLO + bb + 64);

                float    accf[4] = {0.f, 0.f, 0.f, 0.f};
                uint32_t acch[2] = {0u, 0u};

                // main term (fp32 accum): Ahi . Bhi
                mma16816(accf, ah[0], bh + 0);
                mma16816(accf, ah[1], bh + 2);
                mma16816(accf, ah[2], bh + 4);
                mma16816(accf, ah[3], bh + 6);
                // correction terms (fp16 accum): Ahi.Blo + Alo.Bhi
                mmah16816(acch, ah[0], bl + 0);
                mmah16816(acch, ah[1], bl + 2);
                mmah16816(acch, ah[2], bl + 4);
                mmah16816(acch, ah[3], bl + 6);
                mmah16816(acch, al[0], bh + 0);
                mmah16816(acch, al[1], bh + 2);
                mmah16816(acch, al[2], bh + 4);
                mmah16816(acch, al[3], bh + 6);

                // score: dist/2 = 0.5||e||^2 - (main + corr)
                __half2 ch0 = *reinterpret_cast<__half2*>(&acch[0]); // row r0
                __half2 ch1 = *reinterpret_cast<__half2*>(&acch[1]); // row r0+8
                float cr00 = __half2float(__low2half(ch0));
                float cr01 = __half2float(__high2half(ch0));
                float cr10 = __half2float(__low2half(ch1));
                float cr11 = __half2float(__high2half(ch1));

                int cbase = c0 + nt * 8 + (lane & 3) * 2;
                float e0 = se2[cbase], e1 = se2[cbase + 1];
                float s00 = e0 - (accf[0] + cr00);
                float s01 = e1 - (accf[1] + cr01);
                float s10 = e0 - (accf[2] + cr10);
                float s11 = e1 - (accf[3] + cr11);
                if (s00 < best0) { best0 = s00; bi0 = cbase; }
                if (s01 < best0) { best0 = s01; bi0 = cbase + 1; }
                if (s10 < best1) { best1 = s10; bi1 = cbase; }
                if (s11 < best1) { best1 = s11; bi1 = cbase + 1; }
            }
        }

        // reduce across the 4 lanes sharing each row (lane&3 groups)
#pragma unroll
        for (int m = 1; m <= 2; m <<= 1) {
            float o0 = __shfl_xor_sync(0xffffffffu, best0, m);
            int   i0 = __shfl_xor_sync(0xffffffffu, bi0, m);
            float o1 = __shfl_xor_sync(0xffffffffu, best1, m);
            int   i1 = __shfl_xor_sync(0xffffffffu, bi1, m);
            if (o0 < best0 || (o0 == best0 && i0 < bi0)) { best0 = o0; bi0 = i0; }
            if (o1 < best1 || (o1 == best1 && i1 < bi1)) { best1 = o1; bi1 = i1; }
        }
        if ((lane & 3) == 0) {
            int gp = P0 + R0 + (lane >> 2);
            g_best[half * NPIX + gp]     = best0;
            g_bidx[half * NPIX + gp]     = kbase + bi0;
            g_best[half * NPIX + gp + 8] = best1;
            g_bidx[half * NPIX + gp + 8] = kbase + bi1;
        }
        __syncthreads();   // A buffer reusable
    }
}

// ---- combine: 4 threads per pixel (one per 16-dim quarter) ----
__global__ void __launch_bounds__(256)
combine_kernel(const float* __restrict__ cb, float* __restrict__ out) {
    const int tid = threadIdx.x;
    const int px  = tid & 63;            // pixel within CTA's 64
    const int h   = tid >> 6;            // dim quarter: 0..3
    const int p   = blockIdx.x * 64 + px;

    float b0 = g_best[p], b1 = g_best[NPIX + p];
    int k = (b0 <= b1) ? g_bidx[p] : g_bidx[NPIX + p];

    const int b  = p >> 10;
    const int nl = p & (HW - 1);
    float* ob = out + (size_t)b * DIM * HW + nl + (size_t)(h * 16) * HW;

    const float4* crow = (const float4*)(cb + k * DIM + h * 16);
#pragma unroll
    for (int j = 0; j < 4; j++) {
        float4 v = crow[j];
        ob[(size_t)(4 * j + 0) * HW] = v.x;
        ob[(size_t)(4 * j + 1) * HW] = v.y;
        ob[(size_t)(4 * j + 2) * HW] = v.z;
        ob[(size_t)(4 * j + 3) * HW] = v.w;
    }
}

extern "C" void kernel_launch(void* const* d_in, const int* in_sizes, int n_in,
                              void* d_out, int out_size) {
    const float* x  = (const float*)d_in[0];   // (64, 64, 32, 32) fp32
    const float* cb = (const float*)d_in[1];   // (512, 64) fp32
    float* out = (float*)d_out;

    cudaFuncSetAttribute(vq_main, cudaFuncAttributeMaxDynamicSharedMemorySize,
                         SMEM_SZ);

    vq_main<<<GRID, THREADS, SMEM_SZ>>>(x, cb);
    combine_kernel<<<NPIX / 64, 256>>>(cb, out);
}

// round 10
// speedup vs baseline: 1.0387x; 1.0387x over previous
#include <cuda_runtime.h>
#include <cuda_fp16.h>
#include <cstdint>

#define NPIX    65536
#define HW      1024
#define DIM     64
#define KCODES  512
#define TILE_M  256          // pixels per tile
#define NTILES  256
#define GRID    148
#define THREADS 512

// smem byte offsets; rows padded to 144B (72 halves) -> conflict-free ldmatrix
#define ROWB    144
#define OFF_AHI 0
#define OFF_ALO (OFF_AHI + TILE_M * ROWB)    // 36864
#define OFF_BHI (OFF_ALO + TILE_M * ROWB)    // 73728
#define OFF_BLO (OFF_BHI + KCODES * ROWB)    // 147456
#define OFF_E2  (OFF_BLO + KCODES * ROWB)    // 221184
#define OFF_KW  (OFF_E2 + KCODES * 4)        // 223232
#define SMEM_SZ (OFF_KW + TILE_M * 4)        // 224256

static __device__ __forceinline__ uint32_t s2u(const void* p) {
    uint32_t a;
    asm("{ .reg .u64 t; cvta.to.shared.u64 t, %1; cvt.u32.u64 %0, t; }"
        : "=r"(a) : "l"(p));
    return a;
}

#define LDSM_X4(r, addr) \
    asm volatile("ldmatrix.sync.aligned.m8n8.x4.shared.b16 {%0,%1,%2,%3}, [%4];" \
        : "=r"((r)[0]), "=r"((r)[1]), "=r"((r)[2]), "=r"((r)[3]) : "r"(addr))

static __device__ __forceinline__ void mma16816(float* d, const uint32_t* a,
                                                const uint32_t* b) {
    asm volatile(
        "mma.sync.aligned.m16n8k16.row.col.f32.f16.f16.f32 "
        "{%0,%1,%2,%3}, {%4,%5,%6,%7}, {%8,%9}, {%0,%1,%2,%3};"
        : "+f"(d[0]), "+f"(d[1]), "+f"(d[2]), "+f"(d[3])
        : "r"(a[0]), "r"(a[1]), "r"(a[2]), "r"(a[3]), "r"(b[0]), "r"(b[1]));
}

__global__ void __launch_bounds__(THREADS, 1)
vq_fused(const float* __restrict__ x, const float* __restrict__ cb,
         float* __restrict__ out) {
    extern __shared__ char smem[];
    const uint32_t sb = s2u(smem);
    const int tid  = threadIdx.x;
    const int wid  = tid >> 5, lane = tid & 31;

    // ---- stage full codebook (512 codes) as fp16 hi/lo, padded rows ----
    {
        const float4* cb4 = reinterpret_cast<const float4*>(cb);
#pragma unroll
        for (int i = 0; i < (KCODES * DIM / 4) / THREADS; i++) {   // 16 iters
            int idx = i * THREADS + tid;          // 0..8191
            int kr = idx >> 4, d4 = idx & 15;
            float4 v = cb4[idx];
            __half hh[4], ll[4];
            hh[0] = __float2half_rn(v.x); ll[0] = __float2half_rn(v.x - __half2float(hh[0]));
            hh[1] = __float2half_rn(v.y); ll[1] = __float2half_rn(v.y - __half2float(hh[1]));
            hh[2] = __float2half_rn(v.z); ll[2] = __float2half_rn(v.z - __half2float(hh[2]));
            hh[3] = __float2half_rn(v.w); ll[3] = __float2half_rn(v.w - __half2float(hh[3]));
            uint32_t off = kr * ROWB + d4 * 8;
            *(uint2*)(smem + OFF_BHI + off) = *(const uint2*)hh;
            *(uint2*)(smem + OFF_BLO + off) = *(const uint2*)ll;
        }
        // e2: thread k computes 0.5*||code_k||^2
        const float4* row = reinterpret_cast<const float4*>(cb + tid * DIM);
        float s = 0.f;
#pragma unroll
        for (int j = 0; j < DIM / 4; j++) {
            float4 v = row[j];
            s = fmaf(v.x, v.x, s);
            s = fmaf(v.y, v.y, s);
            s = fmaf(v.z, v.z, s);
            s = fmaf(v.w, v.w, s);
        }
        ((float*)(smem + OFF_E2))[tid] = 0.5f * s;
    }
    __syncthreads();

    const float* se2 = (const float*)(smem + OFF_E2);
    int* kwin = (int*)(smem + OFF_KW);
    const int R0 = wid * 16;   // warp's pixel-row base within tile

    for (int t = blockIdx.x; t < NTILES; t += GRID) {
        const int P0  = t * TILE_M;
        const int b   = P0 >> 10;
        const int nl0 = P0 & (HW - 1);
        const float* src = x + (size_t)b * DIM * HW + nl0;

        // ---- stage A tile (256 px x 64 d) fp16 hi/lo, [pixel][dim] ----
        {
            const int row = tid & 255;
            const int d0  = (tid >> 8) * 32;
#pragma unroll
            for (int blk = 0; blk < 4; blk++) {
                __half hh[8], ll[8];
#pragma unroll
                for (int j = 0; j < 8; j++) {
                    float v = src[(size_t)(d0 + blk * 8 + j) * HW + row];
                    hh[j] = __float2half_rn(v);
                    ll[j] = __float2half_rn(v - __half2float(hh[j]));
                }
                uint32_t off = row * ROWB + (d0 + blk * 8) * 2;
                *(uint4*)(smem + OFF_AHI + off) = *(const uint4*)hh;
                *(uint4*)(smem + OFF_ALO + off) = *(const uint4*)ll;
            }
        }
        __syncthreads();

        float best0 = 3.4e38f, best1 = 3.4e38f;
        int   bi0 = 0, bi1 = 0;

        // A ldmatrix address: lane -> row R0+(lane&15), col-half (lane>>4)
        const uint32_t aoff = (R0 + (lane & 15)) * ROWB + (lane >> 4) * 16;
        // B ldmatrix address: lane -> code row (lane&7), 16B chunk (lane>>3)
        const uint32_t boff_lane = (lane & 7) * ROWB + (lane >> 3) * 16;

        for (int c0 = 0; c0 < KCODES; c0 += 64) {     // 8 chunks of 64 codes
            float acc[8][4];
#pragma unroll
            for (int nt = 0; nt < 8; nt++)
#pragma unroll
                for (int j = 0; j < 4; j++) acc[nt][j] = 0.f;

#pragma unroll
            for (int kp = 0; kp < 2; kp++) {          // pairs of k-steps
                uint32_t ah[2][4], al[2][4];
#pragma unroll
                for (int ks = 0; ks < 2; ks++) {
                    uint32_t q = (kp * 2 + ks) * 32;  // 16 dims = 32B
                    LDSM_X4(ah[ks], sb + OFF_AHI + aoff + q);
                    LDSM_X4(al[ks], sb + OFF_ALO + aoff + q);
                }
#pragma unroll
                for (int nt = 0; nt < 8; nt++) {
                    uint32_t bb = (c0 + nt * 8) * ROWB + kp * 64 + boff_lane;
                    uint32_t bh[4], bl[4];
                    LDSM_X4(bh, sb + OFF_BHI + bb);
                    LDSM_X4(bl, sb + OFF_BLO + bb);
                    mma16816(acc[nt], ah[0], bh + 0);
                    mma16816(acc[nt], ah[1], bh + 2);
                    mma16816(acc[nt], ah[0], bl + 0);
                    mma16816(acc[nt], ah[1], bl + 2);
                    mma16816(acc[nt], al[0], bh + 0);
                    mma16816(acc[nt], al[1], bh + 2);
                }
            }

            // score: dist/2 = 0.5*||e||^2 - dot ; rows r0=(lane>>2), r1=r0+8
#pragma unroll
            for (int nt = 0; nt < 8; nt++) {
                int cbase = c0 + nt * 8 + (lane & 3) * 2;
#pragma unroll
                for (int j = 0; j < 2; j++) {
                    float e = se2[cbase + j];
                    int   c = cbase + j;
                    float s0 = e - acc[nt][j];
                    float s1 = e - acc[nt][2 + j];
                    if (s0 < best0) { best0 = s0; bi0 = c; }
                    if (s1 < best1) { best1 = s1; bi1 = c; }
                }
            }
        }

        // reduce across the 4 lanes sharing each row (lane&3 groups)
#pragma unroll
        for (int m = 1; m <= 2; m <<= 1) {
            float o0 = __shfl_xor_sync(0xffffffffu, best0, m);
            int   i0 = __shfl_xor_sync(0xffffffffu, bi0, m);
            float o1 = __shfl_xor_sync(0xffffffffu, best1, m);
            int   i1 = __shfl_xor_sync(0xffffffffu, bi1, m);
            if (o0 < best0 || (o0 == best0 && i0 < bi0)) { best0 = o0; bi0 = i0; }
            if (o1 < best1 || (o1 == best1 && i1 < bi1)) { best1 = o1; bi1 = i1; }
        }
        if ((lane & 3) == 0) {
            kwin[R0 + (lane >> 2)]     = bi0;
            kwin[R0 + (lane >> 2) + 8] = bi1;
        }
        __syncthreads();

        // ---- epilogue: gather winners from smem B (hi+lo), write output ----
        {
            const int px = tid & 255;
            const int h  = tid >> 8;            // dim half 0/1 (32 dims each)
            const int k  = kwin[px];
            const char* bh = smem + OFF_BHI + k * ROWB + h * 64;
            const char* bl = smem + OFF_BLO + k * ROWB + h * 64;
            float* ob = out + (size_t)b * DIM * HW + nl0 + px
                            + (size_t)(h * 32) * HW;
#pragma unroll
            for (int j = 0; j < 4; j++) {
                uint4 H = *(const uint4*)(bh + j * 16);
                uint4 L = *(const uint4*)(bl + j * 16);
                const uint32_t* Hw = &H.x;
                const uint32_t* Lw = &L.x;
#pragma unroll
                for (int e = 0; e < 4; e++) {
                    __half2 h2 = *reinterpret_cast<const __half2*>(&Hw[e]);
                    __half2 l2 = *reinterpret_cast<const __half2*>(&Lw[e]);
                    float v0 = __half2float(__low2half(h2))  + __half2float(__low2half(l2));
                    float v1 = __half2float(__high2half(h2)) + __half2float(__high2half(l2));
                    ob[(size_t)(j * 8 + 2 * e)     * HW] = v0;
                    ob[(size_t)(j * 8 + 2 * e + 1) * HW] = v1;
                }
            }
        }
        // next iteration's A-stage writes A (disjoint from B/kwin reads above);
        // its trailing __syncthreads orders everything before kwin is rewritten
    }
}

extern "C" void kernel_launch(void* const* d_in, const int* in_sizes, int n_in,
                              void* d_out, int out_size) {
    const float* x  = (const float*)d_in[0];   // (64, 64, 32, 32) fp32
    const float* cb = (const float*)d_in[1];   // (512, 64) fp32
    float* out = (float*)d_out;

    cudaFuncSetAttribute(vq_fused, cudaFuncAttributeMaxDynamicSharedMemorySize,
                         SMEM_SZ);

    vq_fused<<<GRID, THREADS, SMEM_SZ>>>(x, cb, out);
}